// round 16
// baseline (speedup 1.0000x reference)
#include <cuda_runtime.h>

// Residual_74629351735837 — bundle-adjustment reprojection residual.
// R16: R12 memory-op mix (proven optimal: stride-7 smem table, 7x LDS.32
// gather, vectorized streaming, ci/pi prefetch) restructured for LOW REGISTER
// PRESSURE (per-point sequential pose gather, pairwise output stores) to run
// 3 blocks/SM (48 warps) instead of 2 (32) -> saturate the L1tex pipe.
// NUMERICS FROZEN: compute_one matched reference at rel_err 9.9e-4.

__device__ __forceinline__ void compute_one(
    float tx, float ty, float tz, float qx, float qy, float qz, float qw,
    float px, float py, float pz,
    float k00, float k01, float k02, float k10, float k11, float k12,
    float k20, float k21, float k22,
    float obx, float oby, float& rx, float& ry)
{
    float crx = __fmaf_rn(qy, pz, -__fmul_rn(qz, py));
    float cry = __fmaf_rn(qz, px, -__fmul_rn(qx, pz));
    float crz = __fmaf_rn(qx, py, -__fmul_rn(qy, px));
    float ux = __fmaf_rn(qw, px, crx);
    float uy = __fmaf_rn(qw, py, cry);
    float uz = __fmaf_rn(qw, pz, crz);
    float cx2 = __fmaf_rn(qy, uz, -__fmul_rn(qz, uy));
    float cy2 = __fmaf_rn(qz, ux, -__fmul_rn(qx, uz));
    float cz2 = __fmaf_rn(qx, uy, -__fmul_rn(qy, ux));
    float X = __fadd_rn(__fmaf_rn(2.0f, cx2, px), tx);
    float Y = __fadd_rn(__fmaf_rn(2.0f, cy2, py), ty);
    float Z = __fadd_rn(__fmaf_rn(2.0f, cz2, pz), tz);
    float pr0 = __fmaf_rn(Z, k02, __fmaf_rn(Y, k01, __fmul_rn(X, k00)));
    float pr1 = __fmaf_rn(Z, k12, __fmaf_rn(Y, k11, __fmul_rn(X, k10)));
    float pr2 = __fmaf_rn(Z, k22, __fmaf_rn(Y, k21, __fmul_rn(X, k20)));
    rx = __fsub_rn(__fdiv_rn(pr0, pr2), obx);
    ry = __fsub_rn(__fdiv_rn(pr1, pr2), oby);
}

__global__ __launch_bounds__(512, 3) void residual_smem_kernel(
    const float* __restrict__ poses,
    const float* __restrict__ points,
    const float* __restrict__ observes,
    const float* __restrict__ Kmat,
    const int* __restrict__ cidx,
    const int* __restrict__ pidx,
    float* __restrict__ out,
    int P, int nPoseFloats)
{
    extern __shared__ float sm_poses[];

    int tid = threadIdx.x;
    // Cooperative stage of the pose table (float4 main + scalar tail).
    int nv4 = nPoseFloats >> 2;
    const float4* pose4 = (const float4*)poses;
    float4* sm4 = (float4*)sm_poses;
    for (int i = tid; i < nv4; i += blockDim.x) sm4[i] = __ldg(pose4 + i);
    for (int i = (nv4 << 2) + tid; i < nPoseFloats; i += blockDim.x)
        sm_poses[i] = __ldg(poses + i);
    __syncthreads();

    // Warp-uniform: expect UR promotion (no GPR cost).
    float k00 = __ldg(Kmat + 0), k01 = __ldg(Kmat + 1), k02 = __ldg(Kmat + 2);
    float k10 = __ldg(Kmat + 3), k11 = __ldg(Kmat + 4), k12 = __ldg(Kmat + 5);
    float k20 = __ldg(Kmat + 6), k21 = __ldg(Kmat + 7), k22 = __ldg(Kmat + 8);

    int G = (P + 3) >> 2;
    int stride = gridDim.x * blockDim.x;
    int t = blockIdx.x * blockDim.x + tid;
    if (t >= G) return;

    // Light prefetch: only next iteration's index vectors.
    bool full = (t * 4 + 3 < P);
    int4 ci, pi;
    if (full) {
        ci = __ldg((const int4*)cidx + t);
        pi = __ldg((const int4*)pidx + t);
    }

    while (t < G) {
        int tn = t + stride;
        bool full_n = (tn < G) && (tn * 4 + 3 < P);
        int4 ci_n, pi_n;
        if (full_n) {
            ci_n = __ldg((const int4*)cidx + tn);
            pi_n = __ldg((const int4*)pidx + tn);
        }

        int base = t * 4;
        if (full) {
            const float4* pbase = (const float4*)points + 3 * t;
            float4 pa = __ldg(pbase + 0);
            float4 pb = __ldg(pbase + 1);
            float4 pd = __ldg(pbase + 2);
            const float4* obp = (const float4*)observes + 2 * t;
            float4 o0 = __ldg(obp + 0);
            float4 o1 = __ldg(obp + 1);

            float pxv[4], pyv[4], pzv[4];
            bool ident = (pi.x == base) & (pi.y == base + 1) &
                         (pi.z == base + 2) & (pi.w == base + 3);
            if (ident) {
                pxv[0] = pa.x; pyv[0] = pa.y; pzv[0] = pa.z;
                pxv[1] = pa.w; pyv[1] = pb.x; pzv[1] = pb.y;
                pxv[2] = pb.z; pyv[2] = pb.w; pzv[2] = pd.x;
                pxv[3] = pd.y; pyv[3] = pd.z; pzv[3] = pd.w;
            } else {
                int piv[4] = {pi.x, pi.y, pi.z, pi.w};
#pragma unroll
                for (int j = 0; j < 4; j++) {
                    const float* pt = points + (long long)piv[j] * 3;
                    pxv[j] = __ldg(pt + 0); pyv[j] = __ldg(pt + 1); pzv[j] = __ldg(pt + 2);
                }
            }

            int civ[4] = {ci.x, ci.y, ci.z, ci.w};
            float obxv[4] = {o0.x, o0.z, o1.x, o1.z};
            float obyv[4] = {o0.y, o0.w, o1.y, o1.w};

            // Per-point sequential: gather pose j, compute j, store pairwise.
            float rx0, ry0, rx1, ry1;
            float4* ov = (float4*)out + 2 * t;
#pragma unroll
            for (int j = 0; j < 4; j++) {
                const float* sp = sm_poses + civ[j] * 7;
                float rx, ry;
                compute_one(sp[0], sp[1], sp[2], sp[3], sp[4], sp[5], sp[6],
                            pxv[j], pyv[j], pzv[j],
                            k00, k01, k02, k10, k11, k12, k20, k21, k22,
                            obxv[j], obyv[j], rx, ry);
                if (j == 0) { rx0 = rx; ry0 = ry; }
                else if (j == 1) { ov[0] = make_float4(rx0, ry0, rx, ry); }
                else if (j == 2) { rx1 = rx; ry1 = ry; }
                else { ov[1] = make_float4(rx1, ry1, rx, ry); }
            }
        } else {
            for (int i = base; i < P; i++) {
                int c = __ldg(cidx + i);
                int p = __ldg(pidx + i);
                const float* sp = sm_poses + c * 7;
                const float* pt = points + (long long)p * 3;
                float rx, ry;
                compute_one(sp[0], sp[1], sp[2], sp[3], sp[4], sp[5], sp[6],
                            __ldg(pt + 0), __ldg(pt + 1), __ldg(pt + 2),
                            k00, k01, k02, k10, k11, k12, k20, k21, k22,
                            __ldg(observes + 2 * i), __ldg(observes + 2 * i + 1),
                            rx, ry);
                out[2 * i] = rx;
                out[2 * i + 1] = ry;
            }
        }

        t = tn; full = full_n; ci = ci_n; pi = pi_n;
    }
}

// Fallback for oversized pose tables: plain gmem gather.
__global__ __launch_bounds__(128) void residual_gmem_kernel(
    const float* __restrict__ poses,
    const float* __restrict__ points,
    const float* __restrict__ observes,
    const float* __restrict__ Kmat,
    const int* __restrict__ cidx,
    const int* __restrict__ pidx,
    float* __restrict__ out,
    int P)
{
    int i = blockIdx.x * blockDim.x + threadIdx.x;
    if (i >= P) return;
    float k00 = __ldg(Kmat + 0), k01 = __ldg(Kmat + 1), k02 = __ldg(Kmat + 2);
    float k10 = __ldg(Kmat + 3), k11 = __ldg(Kmat + 4), k12 = __ldg(Kmat + 5);
    float k20 = __ldg(Kmat + 6), k21 = __ldg(Kmat + 7), k22 = __ldg(Kmat + 8);
    int c = __ldg(cidx + i);
    int p = __ldg(pidx + i);
    const float* pose = poses + (long long)c * 7;
    const float* pt = points + (long long)p * 3;
    float rx, ry;
    compute_one(__ldg(pose + 0), __ldg(pose + 1), __ldg(pose + 2),
                __ldg(pose + 3), __ldg(pose + 4), __ldg(pose + 5), __ldg(pose + 6),
                __ldg(pt + 0), __ldg(pt + 1), __ldg(pt + 2),
                k00, k01, k02, k10, k11, k12, k20, k21, k22,
                __ldg(observes + 2 * i), __ldg(observes + 2 * i + 1), rx, ry);
    out[2 * i] = rx;
    out[2 * i + 1] = ry;
}

extern "C" void kernel_launch(void* const* d_in, const int* in_sizes, int n_in,
                              void* d_out, int out_size)
{
    const float* poses    = (const float*)d_in[0];
    const float* points   = (const float*)d_in[1];
    const float* observes = (const float*)d_in[2];
    const float* Kmat     = (const float*)d_in[3];
    const int*   cidx     = (const int*)d_in[4];
    const int*   pidx     = (const int*)d_in[5];
    float*       out      = (float*)d_out;

    int P = in_sizes[4];
    int nPoseFloats = in_sizes[0];          // C * 7
    size_t smemBytes = (size_t)nPoseFloats * sizeof(float);

    if (smemBytes <= 72 * 1024) {           // 3 blocks/SM needs <= ~75KB each
        static bool attrSet = false;
        if (!attrSet) {
            cudaFuncSetAttribute(residual_smem_kernel,
                                 cudaFuncAttributeMaxDynamicSharedMemorySize,
                                 227 * 1024);
            attrSet = true;
        }
        const int threads = 512;
        int G = (P + 3) >> 2;
        int maxBlocks = 3 * 148;   // 3 blocks/SM = 48 warps/SM
        int needBlocks = (G + threads - 1) / threads;
        int blocks = needBlocks < maxBlocks ? needBlocks : maxBlocks;
        residual_smem_kernel<<<blocks, threads, smemBytes>>>(
            poses, points, observes, Kmat, cidx, pidx, out, P, nPoseFloats);
    } else {
        const int threads = 128;
        int blocks = (P + threads - 1) / threads;
        residual_gmem_kernel<<<blocks, threads>>>(
            poses, points, observes, Kmat, cidx, pidx, out, P);
    }
}

// round 17
// speedup vs baseline: 1.1739x; 1.1739x over previous
#include <cuda_runtime.h>

// Residual_74629351735837 — bundle-adjustment reprojection residual.
// R17 = R12 (proven best, 37.3us) + evict-first streaming hints (__ldcs/__stcs)
// on the zero-reuse streams. Structure/op-mix/registers identical to R12:
//   stride-7 smem pose table, 7x LDS.32 gather, 4 pts/thread, ci/pi prefetch,
//   512 threads x 296 persistent blocks (2/SM, 32 warps/SM, regs ~64).
// NUMERICS FROZEN: compute_one matched reference at rel_err 9.9e-4.

__device__ __forceinline__ void compute_one(
    float tx, float ty, float tz, float qx, float qy, float qz, float qw,
    float px, float py, float pz,
    float k00, float k01, float k02, float k10, float k11, float k12,
    float k20, float k21, float k22,
    float obx, float oby, float& rx, float& ry)
{
    float crx = __fmaf_rn(qy, pz, -__fmul_rn(qz, py));
    float cry = __fmaf_rn(qz, px, -__fmul_rn(qx, pz));
    float crz = __fmaf_rn(qx, py, -__fmul_rn(qy, px));
    float ux = __fmaf_rn(qw, px, crx);
    float uy = __fmaf_rn(qw, py, cry);
    float uz = __fmaf_rn(qw, pz, crz);
    float cx2 = __fmaf_rn(qy, uz, -__fmul_rn(qz, uy));
    float cy2 = __fmaf_rn(qz, ux, -__fmul_rn(qx, uz));
    float cz2 = __fmaf_rn(qx, uy, -__fmul_rn(qy, ux));
    float X = __fadd_rn(__fmaf_rn(2.0f, cx2, px), tx);
    float Y = __fadd_rn(__fmaf_rn(2.0f, cy2, py), ty);
    float Z = __fadd_rn(__fmaf_rn(2.0f, cz2, pz), tz);
    float pr0 = __fmaf_rn(Z, k02, __fmaf_rn(Y, k01, __fmul_rn(X, k00)));
    float pr1 = __fmaf_rn(Z, k12, __fmaf_rn(Y, k11, __fmul_rn(X, k10)));
    float pr2 = __fmaf_rn(Z, k22, __fmaf_rn(Y, k21, __fmul_rn(X, k20)));
    rx = __fsub_rn(__fdiv_rn(pr0, pr2), obx);
    ry = __fsub_rn(__fdiv_rn(pr1, pr2), oby);
}

__global__ __launch_bounds__(512, 2) void residual_smem_kernel(
    const float* __restrict__ poses,
    const float* __restrict__ points,
    const float* __restrict__ observes,
    const float* __restrict__ Kmat,
    const int* __restrict__ cidx,
    const int* __restrict__ pidx,
    float* __restrict__ out,
    int P, int nPoseFloats)
{
    extern __shared__ float sm_poses[];

    int tid = threadIdx.x;
    // Cooperative stage of the pose table (float4 main + scalar tail).
    int nv4 = nPoseFloats >> 2;
    const float4* pose4 = (const float4*)poses;
    float4* sm4 = (float4*)sm_poses;
    for (int i = tid; i < nv4; i += blockDim.x) sm4[i] = __ldg(pose4 + i);
    for (int i = (nv4 << 2) + tid; i < nPoseFloats; i += blockDim.x)
        sm_poses[i] = __ldg(poses + i);
    __syncthreads();

    float k00 = __ldg(Kmat + 0), k01 = __ldg(Kmat + 1), k02 = __ldg(Kmat + 2);
    float k10 = __ldg(Kmat + 3), k11 = __ldg(Kmat + 4), k12 = __ldg(Kmat + 5);
    float k20 = __ldg(Kmat + 6), k21 = __ldg(Kmat + 7), k22 = __ldg(Kmat + 8);

    int G = (P + 3) >> 2;
    int stride = gridDim.x * blockDim.x;
    int t = blockIdx.x * blockDim.x + tid;
    if (t >= G) return;

    // Light prefetch: only next iteration's index vectors (evict-first).
    bool full = (t * 4 + 3 < P);
    int4 ci, pi;
    if (full) {
        ci = __ldcs((const int4*)cidx + t);
        pi = __ldcs((const int4*)pidx + t);
    }

    while (t < G) {
        int tn = t + stride;
        bool full_n = (tn < G) && (tn * 4 + 3 < P);
        int4 ci_n, pi_n;
        if (full_n) {
            ci_n = __ldcs((const int4*)cidx + tn);
            pi_n = __ldcs((const int4*)pidx + tn);
        }

        int base = t * 4;
        if (full) {
            // Streaming loads for this iteration (zero reuse -> evict-first).
            const float4* pbase = (const float4*)points + 3 * t;
            float4 pa = __ldcs(pbase + 0);
            float4 pb = __ldcs(pbase + 1);
            float4 pd = __ldcs(pbase + 2);
            const float4* obp = (const float4*)observes + 2 * t;
            float4 o0 = __ldcs(obp + 0);
            float4 o1 = __ldcs(obp + 1);

            float pxv[4], pyv[4], pzv[4];
            bool ident = (pi.x == base) & (pi.y == base + 1) &
                         (pi.z == base + 2) & (pi.w == base + 3);
            if (ident) {
                pxv[0] = pa.x; pyv[0] = pa.y; pzv[0] = pa.z;
                pxv[1] = pa.w; pyv[1] = pb.x; pzv[1] = pb.y;
                pxv[2] = pb.z; pyv[2] = pb.w; pzv[2] = pd.x;
                pxv[3] = pd.y; pyv[3] = pd.z; pzv[3] = pd.w;
            } else {
                int piv[4] = {pi.x, pi.y, pi.z, pi.w};
#pragma unroll
                for (int j = 0; j < 4; j++) {
                    const float* pt = points + (long long)piv[j] * 3;
                    pxv[j] = __ldg(pt + 0); pyv[j] = __ldg(pt + 1); pzv[j] = __ldg(pt + 2);
                }
            }

            int civ[4] = {ci.x, ci.y, ci.z, ci.w};
            float txv[4], tyv[4], tzv[4], qxv[4], qyv[4], qzv[4], qwv[4];
#pragma unroll
            for (int j = 0; j < 4; j++) {
                const float* sp = sm_poses + civ[j] * 7;
                txv[j] = sp[0]; tyv[j] = sp[1]; tzv[j] = sp[2];
                qxv[j] = sp[3]; qyv[j] = sp[4]; qzv[j] = sp[5];
                qwv[j] = sp[6];
            }

            float obx[4] = {o0.x, o0.z, o1.x, o1.z};
            float oby[4] = {o0.y, o0.w, o1.y, o1.w};

            float rx[4], ry[4];
#pragma unroll
            for (int j = 0; j < 4; j++) {
                compute_one(txv[j], tyv[j], tzv[j], qxv[j], qyv[j], qzv[j], qwv[j],
                            pxv[j], pyv[j], pzv[j],
                            k00, k01, k02, k10, k11, k12, k20, k21, k22,
                            obx[j], oby[j], rx[j], ry[j]);
            }

            float4* ov = (float4*)out + 2 * t;
            __stcs(ov + 0, make_float4(rx[0], ry[0], rx[1], ry[1]));
            __stcs(ov + 1, make_float4(rx[2], ry[2], rx[3], ry[3]));
        } else {
            for (int i = base; i < P; i++) {
                int c = __ldg(cidx + i);
                int p = __ldg(pidx + i);
                const float* sp = sm_poses + c * 7;
                const float* pt = points + (long long)p * 3;
                float rx, ry;
                compute_one(sp[0], sp[1], sp[2], sp[3], sp[4], sp[5], sp[6],
                            __ldg(pt + 0), __ldg(pt + 1), __ldg(pt + 2),
                            k00, k01, k02, k10, k11, k12, k20, k21, k22,
                            __ldg(observes + 2 * i), __ldg(observes + 2 * i + 1),
                            rx, ry);
                out[2 * i] = rx;
                out[2 * i + 1] = ry;
            }
        }

        t = tn; full = full_n; ci = ci_n; pi = pi_n;
    }
}

// Fallback for oversized pose tables: plain gmem gather.
__global__ __launch_bounds__(128) void residual_gmem_kernel(
    const float* __restrict__ poses,
    const float* __restrict__ points,
    const float* __restrict__ observes,
    const float* __restrict__ Kmat,
    const int* __restrict__ cidx,
    const int* __restrict__ pidx,
    float* __restrict__ out,
    int P)
{
    int i = blockIdx.x * blockDim.x + threadIdx.x;
    if (i >= P) return;
    float k00 = __ldg(Kmat + 0), k01 = __ldg(Kmat + 1), k02 = __ldg(Kmat + 2);
    float k10 = __ldg(Kmat + 3), k11 = __ldg(Kmat + 4), k12 = __ldg(Kmat + 5);
    float k20 = __ldg(Kmat + 6), k21 = __ldg(Kmat + 7), k22 = __ldg(Kmat + 8);
    int c = __ldg(cidx + i);
    int p = __ldg(pidx + i);
    const float* pose = poses + (long long)c * 7;
    const float* pt = points + (long long)p * 3;
    float rx, ry;
    compute_one(__ldg(pose + 0), __ldg(pose + 1), __ldg(pose + 2),
                __ldg(pose + 3), __ldg(pose + 4), __ldg(pose + 5), __ldg(pose + 6),
                __ldg(pt + 0), __ldg(pt + 1), __ldg(pt + 2),
                k00, k01, k02, k10, k11, k12, k20, k21, k22,
                __ldg(observes + 2 * i), __ldg(observes + 2 * i + 1), rx, ry);
    out[2 * i] = rx;
    out[2 * i + 1] = ry;
}

extern "C" void kernel_launch(void* const* d_in, const int* in_sizes, int n_in,
                              void* d_out, int out_size)
{
    const float* poses    = (const float*)d_in[0];
    const float* points   = (const float*)d_in[1];
    const float* observes = (const float*)d_in[2];
    const float* Kmat     = (const float*)d_in[3];
    const int*   cidx     = (const int*)d_in[4];
    const int*   pidx     = (const int*)d_in[5];
    float*       out      = (float*)d_out;

    int P = in_sizes[4];
    int nPoseFloats = in_sizes[0];          // C * 7
    size_t smemBytes = (size_t)nPoseFloats * sizeof(float);

    if (smemBytes <= 100 * 1024) {
        static bool attrSet = false;
        if (!attrSet) {
            cudaFuncSetAttribute(residual_smem_kernel,
                                 cudaFuncAttributeMaxDynamicSharedMemorySize,
                                 227 * 1024);
            attrSet = true;
        }
        const int threads = 512;
        int G = (P + 3) >> 2;
        int maxBlocks = 2 * 148;   // 2 blocks/SM (56KB smem each) = 32 warps/SM
        int needBlocks = (G + threads - 1) / threads;
        int blocks = needBlocks < maxBlocks ? needBlocks : maxBlocks;
        residual_smem_kernel<<<blocks, threads, smemBytes>>>(
            poses, points, observes, Kmat, cidx, pidx, out, P, nPoseFloats);
    } else {
        const int threads = 128;
        int blocks = (P + threads - 1) / threads;
        residual_gmem_kernel<<<blocks, threads>>>(
            poses, points, observes, Kmat, cidx, pidx, out, P);
    }
}